// round 7
// baseline (speedup 1.0000x reference)
#include <cuda_runtime.h>

#define NMAX 16384
#define KNN  16
#define CDIM 64
#define NODES_PER_BLOCK 4

#define KNN_TILE 2048         // candidates per smem tile (32KB packed)
#define SCAN_THREADS 128      // 128 queries per block (thread = query)
#define BUFCAP 64             // per-lane survivor buffer (local mem)
#define MARGIN 2.5f

#define FULLMASK 0xffffffffu
#define FINF __int_as_float(0x7f800000)

// ---- scratch (no allocation allowed) ----
__device__ float4     g_pos4[NMAX];
__device__ ulonglong2 g_pairA[NMAX / 2];   // (x-pair, y-pair) per 2 candidates
__device__ ulonglong2 g_pairB[NMAX / 2];   // (z-pair, w-pair)
__device__ int    g_knn[NMAX * KNN];
__device__ int    g_flag[NMAX];
__device__ float  g_B[NMAX * CDIM];   // x @ W1b
__device__ float  g_C[NMAX * CDIM];   // x @ (W1a - W1b) + b1

// ---- packed f32x2 helpers ----
__device__ __forceinline__ unsigned long long pk2(float a, float b) {
    unsigned long long r;
    asm("mov.b64 %0, {%1, %2};" : "=l"(r) : "f"(a), "f"(b));
    return r;
}
__device__ __forceinline__ void upk2(unsigned long long v, float& a, float& b) {
    asm("mov.b64 {%0, %1}, %2;" : "=f"(a), "=f"(b) : "l"(v));
}
__device__ __forceinline__ unsigned long long fma2(unsigned long long a,
                                                   unsigned long long b,
                                                   unsigned long long c) {
    unsigned long long r;
    asm("fma.rn.f32x2 %0, %1, %2, %3;" : "=l"(r) : "l"(a), "l"(b), "l"(c));
    return r;
}
__device__ __forceinline__ unsigned long long mul2(unsigned long long a,
                                                   unsigned long long b) {
    unsigned long long r;
    asm("mul.rn.f32x2 %0, %1, %2;" : "=l"(r) : "l"(a), "l"(b));
    return r;
}
__device__ __forceinline__ unsigned long long add2(unsigned long long a,
                                                   unsigned long long b) {
    unsigned long long r;
    asm("add.rn.f32x2 %0, %1, %2;" : "=l"(r) : "l"(a), "l"(b));
    return r;
}

// ============================================================
// Kernel 0: pack pos -> float4 (queries) + paired f32x2 layout (candidates)
// ============================================================
__global__ void pack_pos_kernel(const float* __restrict__ pos, int n) {
    int i = blockIdx.x * blockDim.x + threadIdx.x;
    if (i < n / 2) {
        int a = 2 * i, b = 2 * i + 1;
        float xa = pos[a * 3 + 0], ya = pos[a * 3 + 1], za = pos[a * 3 + 2];
        float xb = pos[b * 3 + 0], yb = pos[b * 3 + 1], zb = pos[b * 3 + 2];
        float wa = fmaf(xa, xa, fmaf(ya, ya, za * za));
        float wb = fmaf(xb, xb, fmaf(yb, yb, zb * zb));
        g_pos4[a] = make_float4(xa, ya, za, wa);
        g_pos4[b] = make_float4(xb, yb, zb, wb);
        g_pairA[i] = make_ulonglong2(pk2(xa, xb), pk2(ya, yb));
        g_pairB[i] = make_ulonglong2(pk2(za, zb), pk2(wa, wb));
    }
}

// ============================================================
// Kernel 1a: KNN scan — TRANSPOSED: thread = query, candidates broadcast.
// One LDS.128 broadcast serves all 32 queries of the warp; appends to a
// per-lane local-memory buffer are predicated (no divergent insert loops).
// Threshold = analytic 16-NN radius for N(0,I3) points * safety margin.
// Under/overflow queries are flagged for the exact fallback kernel.
// ============================================================
__global__ __launch_bounds__(SCAN_THREADS, 2)
void knn_scan_kernel(int n) {
    __shared__ ulonglong2 tileA[KNN_TILE / 2];
    __shared__ ulonglong2 tileB[KNN_TILE / 2];

    const int tid = threadIdx.x;
    const int q   = blockIdx.x * SCAN_THREADS + tid;

    const float4 qp = g_pos4[q];
    const unsigned long long qx2 = pk2(qp.x, qp.x);
    const unsigned long long qy2 = pk2(qp.y, qp.y);
    const unsigned long long qz2 = pk2(qp.z, qp.z);
    const unsigned long long qw2 = pk2(qp.w, qp.w);
    const unsigned long long M2  = pk2(-2.0f, -2.0f);

    // analytic threshold: expected #pts within r of q is
    // n * rho(q) * (4pi/3) r^3,  rho(q) = (2pi)^{-3/2} exp(-|q|^2/2)
    // choose r so expected = KNN * MARGIN
    const float c0 = (KNN * MARGIN * 3.0f) /
                     (4.0f * 3.14159265f * 0.06349364f * (float)n);
    const float r3  = c0 * __expf(0.5f * qp.w);
    const float thr = __powf(r3, 0.6666667f);   // r^2

    unsigned long long buf[BUFCAP];
    int cnt = 0;

    for (int t0 = 0; t0 < n; t0 += KNN_TILE) {
        const int pbase = t0 / 2;
        for (int c = tid; c < KNN_TILE / 2; c += SCAN_THREADS) {
            tileA[c] = g_pairA[pbase + c];
            tileB[c] = g_pairB[pbase + c];
        }
        __syncthreads();

#pragma unroll 4
        for (int c = 0; c < KNN_TILE / 2; c += 2) {
            ulonglong2 A0 = tileA[c],     B0 = tileB[c];      // broadcast
            ulonglong2 A1 = tileA[c + 1], B1 = tileB[c + 1];
            unsigned long long a0 = mul2(qz2, B0.x);
            a0 = fma2(qy2, A0.y, a0);
            a0 = fma2(qx2, A0.x, a0);
            unsigned long long dd0 = fma2(M2, a0, add2(qw2, B0.y));
            unsigned long long a1 = mul2(qz2, B1.x);
            a1 = fma2(qy2, A1.y, a1);
            a1 = fma2(qx2, A1.x, a1);
            unsigned long long dd1 = fma2(M2, a1, add2(qw2, B1.y));
            float d0, d1, d2, d3;
            upk2(dd0, d0, d1);
            upk2(dd1, d2, d3);
            bool p0 = d0 < thr, p1 = d1 < thr, p2 = d2 < thr, p3 = d3 < thr;
            if (__any_sync(FULLMASK, p0 | p1 | p2 | p3)) {
                int j0 = t0 + 2 * c;
                if (p0 && j0 != q && cnt < BUFCAP)
                    buf[cnt++] = ((unsigned long long)
                        __float_as_uint(fmaxf(d0, 0.0f)) << 32) | (unsigned)j0;
                if (p1 && j0 + 1 != q && cnt < BUFCAP)
                    buf[cnt++] = ((unsigned long long)
                        __float_as_uint(fmaxf(d1, 0.0f)) << 32) | (unsigned)(j0 + 1);
                if (p2 && j0 + 2 != q && cnt < BUFCAP)
                    buf[cnt++] = ((unsigned long long)
                        __float_as_uint(fmaxf(d2, 0.0f)) << 32) | (unsigned)(j0 + 2);
                if (p3 && j0 + 3 != q && cnt < BUFCAP)
                    buf[cnt++] = ((unsigned long long)
                        __float_as_uint(fmaxf(d3, 0.0f)) << 32) | (unsigned)(j0 + 3);
            }
        }
        __syncthreads();
    }

    // cnt == BUFCAP may have dropped survivors -> must flag
    int bad = (cnt < KNN) | (cnt >= BUFCAP);
    g_flag[q] = bad;
    if (!bad) {
        // select 16 smallest of cnt (packed keys: dist-bits high, idx low)
        for (int r = 0; r < KNN; r++) {
            unsigned long long m = ~0ULL;
            int mi = 0;
            for (int t = 0; t < cnt; t++) {
                unsigned long long v = buf[t];
                if (v < m) { m = v; mi = t; }
            }
            buf[mi] = ~0ULL;
            g_knn[q * KNN + r] = (int)(m & 0xffffffffu);
        }
    }
}

// ============================================================
// Kernel 1b: exact fallback for flagged queries — warp per query,
// warp-distributed sorted top-16 (proven R4/R5 insert), LDG from L2.
// Non-flagged warps exit immediately.
// ============================================================
__device__ __forceinline__ void warp_insert(float dn, int jn,
                                            float& bd, int& bj,
                                            float& worst, int lane) {
    float bp = __shfl_up_sync(FULLMASK, bd, 1);
    int   ip = __shfl_up_sync(FULLMASK, bj, 1);
    unsigned gm = __ballot_sync(FULLMASK, (lane < KNN) && (bd > dn));
    int pos = __ffs(gm) - 1;            // gm != 0 since bd[15] > dn
    if (lane < KNN) {
        if (lane > pos)       { bd = bp; bj = ip; }
        else if (lane == pos) { bd = dn; bj = jn; }
    }
    worst = __shfl_sync(FULLMASK, bd, KNN - 1);
}

__global__ __launch_bounds__(256)
void knn_fallback_kernel(int n) {
    const int lane = threadIdx.x & 31;
    const int q    = blockIdx.x * 8 + (threadIdx.x >> 5);
    if (g_flag[q] == 0) return;       // warp-uniform

    const float4 qp = g_pos4[q];
    const unsigned long long qx2 = pk2(qp.x, qp.x);
    const unsigned long long qy2 = pk2(qp.y, qp.y);
    const unsigned long long qz2 = pk2(qp.z, qp.z);
    const unsigned long long qw2 = pk2(qp.w, qp.w);
    const unsigned long long M2  = pk2(-2.0f, -2.0f);

    float bd = FINF;
    int   bj = 0;
    float worst = FINF;

    for (int base = 0; base < n / 2; base += 32) {
        ulonglong2 A = g_pairA[base + lane];
        ulonglong2 B = g_pairB[base + lane];
        unsigned long long acc = mul2(qz2, B.x);
        acc = fma2(qy2, A.y, acc);
        acc = fma2(qx2, A.x, acc);
        unsigned long long dd = fma2(M2, acc, add2(qw2, B.y));
        float d0, d1;
        upk2(dd, d0, d1);

        unsigned m = __ballot_sync(FULLMASK, (d0 < worst) | (d1 < worst));
        while (m) {
            int src = __ffs(m) - 1;
            m &= m - 1;
            float e0 = __shfl_sync(FULLMASK, d0, src);
            float e1 = __shfl_sync(FULLMASK, d1, src);
            int   j0 = 2 * (base + src);
            if (e0 < worst && j0 != q)
                warp_insert(e0, j0, bd, bj, worst, lane);
            if (e1 < worst && j0 + 1 != q)
                warp_insert(e1, j0 + 1, bd, bj, worst, lane);
        }
    }

    if (lane < KNN)
        g_knn[q * KNN + lane] = bj;
}

// ============================================================
// Kernel 2: B = x @ W1b ; C = x @ (W1a - W1b) + b1
// ============================================================
__global__ void feat_kernel(const float* __restrict__ x,
                            const float* __restrict__ W1,
                            const float* __restrict__ b1, int n) {
    int t = blockIdx.x * blockDim.x + threadIdx.x;
    int nn = t >> 6;
    int d  = t & 63;
    if (nn >= n) return;
    const float* xr = x + nn * CDIM;
    float a = 0.0f, b = 0.0f;
#pragma unroll 8
    for (int c = 0; c < CDIM; c++) {
        float xv = xr[c];                           // warp broadcast, L1-hot
        a = fmaf(xv, W1[c * CDIM + d], a);          // W1a
        b = fmaf(xv, W1[(CDIM + c) * CDIM + d], b); // W1b
    }
    g_B[t] = b;
    g_C[t] = a - b + b1[d];
}

// ============================================================
// Kernel 3: per-node relu + 16x64 matvec + max, SOFTWARE-PIPELINED:
// node i+1's B-row gather (L2, ~250cyc) is issued before phase2 of node
// i, so the latency is hidden under ~600 issue-slots of compute.
// Double-buffered gs -> one __syncthreads per node.
// ============================================================
__global__ __launch_bounds__(64)
void edge_kernel(const float* __restrict__ W2,
                 const float* __restrict__ b2,
                 float* __restrict__ out, int n) {
    __shared__ __align__(16) float gs[2][KNN][CDIM];
    const int d = threadIdx.x;

    // pack W2 column d as 32 f32x2 pairs
    unsigned long long w2p[CDIM / 2];
#pragma unroll
    for (int e2 = 0; e2 < CDIM / 2; e2++)
        w2p[e2] = pk2(W2[(2 * e2) * CDIM + d], W2[(2 * e2 + 1) * CDIM + d]);
    const float b2d = b2[d];

    const int n0 = blockIdx.x * NODES_PER_BLOCK;

    // prologue: prefetch node n0
    float bv[KNN];
    float cv;
    {
        const int4* jr = (const int4*)&g_knn[n0 * KNN];
        int4 j4[4];
#pragma unroll
        for (int v = 0; v < 4; v++) j4[v] = jr[v];
        const int* jv = (const int*)j4;
        cv = g_C[n0 * CDIM + d];
#pragma unroll
        for (int k = 0; k < KNN; k++)
            bv[k] = g_B[jv[k] * CDIM + d];
    }

    for (int i = 0; i < NODES_PER_BLOCK; i++) {
        const int buf = i & 1;
        const int nn  = n0 + i;
        const float cvi = cv;

        // publish prefetched g-rows
#pragma unroll
        for (int k = 0; k < KNN; k++)
            gs[buf][k][d] = fmaxf(cvi + bv[k], 0.0f);

        // prefetch node i+1 (LDG latency hidden under phase2 below)
        if (i + 1 < NODES_PER_BLOCK) {
            const int nn1 = nn + 1;
            const int4* jr = (const int4*)&g_knn[nn1 * KNN];
            int4 j4[4];
#pragma unroll
            for (int v = 0; v < 4; v++) j4[v] = jr[v];
            const int* jv = (const int*)j4;
            cv = g_C[nn1 * CDIM + d];
#pragma unroll
            for (int k = 0; k < KNN; k++)
                bv[k] = g_B[jv[k] * CDIM + d];
        }
        __syncthreads();

        // phase 2: 16 matvecs + max, packed f32x2, 4 chains
        float m = -3.4e38f;
#pragma unroll
        for (int k = 0; k < KNN; k++) {
            const ulonglong2* gp = (const ulonglong2*)gs[buf][k];
            unsigned long long a0 = 0ULL, a1 = 0ULL, a2 = 0ULL, a3 = 0ULL;
#pragma unroll
            for (int e8 = 0; e8 < CDIM / 8; e8++) {
                ulonglong2 g0 = gp[2 * e8];         // LDS.128 broadcast
                ulonglong2 g1 = gp[2 * e8 + 1];
                a0 = fma2(g0.x, w2p[4 * e8 + 0], a0);
                a1 = fma2(g0.y, w2p[4 * e8 + 1], a1);
                a2 = fma2(g1.x, w2p[4 * e8 + 2], a2);
                a3 = fma2(g1.y, w2p[4 * e8 + 3], a3);
            }
            a0 = add2(a0, a1);
            a2 = add2(a2, a3);
            a0 = add2(a0, a2);
            float lo, hi;
            upk2(a0, lo, hi);
            m = fmaxf(m, lo + hi);
        }
        out[nn * CDIM + d] = m + b2d;
    }
}

// ============================================================
extern "C" void kernel_launch(void* const* d_in, const int* in_sizes, int n_in,
                              void* d_out, int out_size) {
    const float* x   = (const float*)d_in[0];
    const float* pos = (const float*)d_in[1];
    const float* W1  = (const float*)d_in[2];
    const float* b1  = (const float*)d_in[3];
    const float* W2  = (const float*)d_in[4];
    const float* b2  = (const float*)d_in[5];
    float* out = (float*)d_out;

    int n = in_sizes[1] / 3;
    if (n > NMAX) n = NMAX;

    pack_pos_kernel<<<(n / 2 + 255) / 256, 256>>>(pos, n);
    knn_scan_kernel<<<n / SCAN_THREADS, SCAN_THREADS>>>(n);
    knn_fallback_kernel<<<n / 8, 256>>>(n);
    feat_kernel<<<(n * CDIM + 255) / 256, 256>>>(x, W1, b1, n);
    edge_kernel<<<n / NODES_PER_BLOCK, CDIM>>>(W2, b2, out, n);
}

// round 8
// speedup vs baseline: 2.1177x; 2.1177x over previous
#include <cuda_runtime.h>

#define NMAX 16384
#define KNN  16
#define CDIM 64
#define NODES_PER_BLOCK 4

#define KNN_WARPS 16          // warps per block; 2 queries per warp
#define KNN_THREADS (KNN_WARPS * 32)
#define KNN_TILE 2048         // candidates per smem tile (32KB packed)
#define MARGIN 3.0f

#define FULLMASK 0xffffffffu
#define FINF __int_as_float(0x7f800000)

// ---- scratch (no allocation allowed) ----
__device__ float4     g_pos4[NMAX];
__device__ ulonglong2 g_pairA[NMAX / 2];   // (x-pair, y-pair) per 2 candidates
__device__ ulonglong2 g_pairB[NMAX / 2];   // (z-pair, w-pair)
__device__ int    g_knn[NMAX * KNN];
__device__ int    g_flag[NMAX];
__device__ float  g_B[NMAX * CDIM];   // x @ W1b
__device__ float  g_C[NMAX * CDIM];   // x @ (W1a - W1b) + b1

// ---- packed f32x2 helpers ----
__device__ __forceinline__ unsigned long long pk2(float a, float b) {
    unsigned long long r;
    asm("mov.b64 %0, {%1, %2};" : "=l"(r) : "f"(a), "f"(b));
    return r;
}
__device__ __forceinline__ void upk2(unsigned long long v, float& a, float& b) {
    asm("mov.b64 {%0, %1}, %2;" : "=f"(a), "=f"(b) : "l"(v));
}
__device__ __forceinline__ unsigned long long fma2(unsigned long long a,
                                                   unsigned long long b,
                                                   unsigned long long c) {
    unsigned long long r;
    asm("fma.rn.f32x2 %0, %1, %2, %3;" : "=l"(r) : "l"(a), "l"(b), "l"(c));
    return r;
}
__device__ __forceinline__ unsigned long long mul2(unsigned long long a,
                                                   unsigned long long b) {
    unsigned long long r;
    asm("mul.rn.f32x2 %0, %1, %2;" : "=l"(r) : "l"(a), "l"(b));
    return r;
}
__device__ __forceinline__ unsigned long long add2(unsigned long long a,
                                                   unsigned long long b) {
    unsigned long long r;
    asm("add.rn.f32x2 %0, %1, %2;" : "=l"(r) : "l"(a), "l"(b));
    return r;
}

// analytic radius^2 such that expected #points within r = KNN*MARGIN
// for pos ~ N(0, I3): rho(q) = (2pi)^{-3/2} exp(-|q|^2/2)
__device__ __forceinline__ float knn_thr(float qw, int n) {
    const float c0 = (KNN * MARGIN * 3.0f) /
                     (4.0f * 3.14159265f * 0.06349364f * (float)n);
    float r3 = c0 * __expf(0.5f * qw);
    return __powf(r3, 0.6666667f);
}

// ============================================================
// Kernel 0: pack pos -> float4 (queries) + paired f32x2 layout (candidates)
// ============================================================
__global__ void pack_pos_kernel(const float* __restrict__ pos, int n) {
    int i = blockIdx.x * blockDim.x + threadIdx.x;
    if (i < n / 2) {
        int a = 2 * i, b = 2 * i + 1;
        float xa = pos[a * 3 + 0], ya = pos[a * 3 + 1], za = pos[a * 3 + 2];
        float xb = pos[b * 3 + 0], yb = pos[b * 3 + 1], zb = pos[b * 3 + 2];
        float wa = fmaf(xa, xa, fmaf(ya, ya, za * za));
        float wb = fmaf(xb, xb, fmaf(yb, yb, zb * zb));
        g_pos4[a] = make_float4(xa, ya, za, wa);
        g_pos4[b] = make_float4(xb, yb, zb, wb);
        g_pairA[i] = make_ulonglong2(pk2(xa, xb), pk2(ya, yb));
        g_pairB[i] = make_ulonglong2(pk2(za, zb), pk2(wa, wb));
    }
}

// ============================================================
// Kernel 1a: KNN scan — 2 queries per warp (16 lanes each), proven R6
// insert logic, but `worst` is SEEDED with the analytic radius so the
// early-flood inserts (~90 of ~130 events) never happen.
// Subgroups that end with <16 survivors are flagged for exact fallback.
// ============================================================
__global__ __launch_bounds__(KNN_THREADS, 4)
void knn_scan_kernel(int n) {
    __shared__ ulonglong2 tileA[KNN_TILE / 2];  // (x-pair, y-pair)
    __shared__ ulonglong2 tileB[KNN_TILE / 2];  // (z-pair, w-pair)

    const int tid  = threadIdx.x;
    const int w    = tid >> 5;
    const int lane = tid & 31;
    const int qs   = lane >> 4;          // subgroup (query within warp)
    const int cs   = lane & 15;          // rank / candidate-pair slot
    const int q    = blockIdx.x * (KNN_WARPS * 2) + w * 2 + qs;

    const float4 qp = g_pos4[q];
    const unsigned long long qx2 = pk2(qp.x, qp.x);
    const unsigned long long qy2 = pk2(qp.y, qp.y);
    const unsigned long long qz2 = pk2(qp.z, qp.z);
    const unsigned long long qw2 = pk2(qp.w, qp.w);
    const unsigned long long M2  = pk2(-2.0f, -2.0f);

    const float thr = knn_thr(qp.w, n);   // subgroup-uniform

    float bd = FINF;      // rank cs of this subgroup's sorted top-16
    int   bj = 0;
    float worst = thr;    // seeded threshold (subgroup-uniform)

    for (int t0 = 0; t0 < n; t0 += KNN_TILE) {
        const int pbase = t0 / 2;
        for (int c = tid; c < KNN_TILE / 2; c += KNN_THREADS) {
            tileA[c] = g_pairA[pbase + c];   // straight LDG.128 -> STS.128
            tileB[c] = g_pairB[pbase + c];
        }
        __syncthreads();

#pragma unroll 4
        for (int it = 0; it < KNN_TILE / 2; it += 16) {
            ulonglong2 A = tileA[it + cs];   // 16 distinct addrs, 2-way bcast
            ulonglong2 B = tileB[it + cs];
            unsigned long long acc = mul2(qz2, B.x);
            acc = fma2(qy2, A.y, acc);
            acc = fma2(qx2, A.x, acc);
            unsigned long long dd = fma2(M2, acc, add2(qw2, B.y));
            float d0, d1;
            upk2(dd, d0, d1);
            int pj = t0 + 2 * (it + cs);     // candidates pj, pj+1

            unsigned mfull = __ballot_sync(FULLMASK, (d0 < worst) | (d1 < worst));
            unsigned m0 = mfull & 0xFFFFu;   // subgroup 0 events
            unsigned m1 = mfull >> 16;       // subgroup 1 events
            while (m0 | m1) {                // warp-uniform
                int s0 = __ffs(m0) - 1;
                int s1 = __ffs(m1) - 1;
                m0 &= m0 - 1;                // (0 & ~0) == 0: safe when empty
                m1 &= m1 - 1;
                bool has = qs ? (s1 >= 0) : (s0 >= 0);
                int  src = qs ? (s1 < 0 ? 16 : 16 + s1)
                              : (s0 < 0 ? 0  : s0);
                float e0 = __shfl_sync(FULLMASK, d0, src);
                float e1 = __shfl_sync(FULLMASK, d1, src);
                int   j0 = __shfl_sync(FULLMASK, pj, src);

                // insert candidate j0 (distance e0)
                {
                    bool act = has && (e0 < worst) && (j0 != q); // sub-uniform
                    float bp = __shfl_up_sync(FULLMASK, bd, 1);
                    int   ip = __shfl_up_sync(FULLMASK, bj, 1);
                    unsigned gm = __ballot_sync(FULLMASK, act && (bd > e0));
                    if (act) {
                        int pos = __ffs((gm >> (qs << 4)) & 0xFFFFu) - 1;
                        if (cs > pos)       { bd = bp; bj = ip; }
                        else if (cs == pos) { bd = fmaxf(e0, 0.0f); bj = j0; }
                    }
                    worst = fminf(thr,
                                  __shfl_sync(FULLMASK, bd, (qs << 4) + 15));
                }
                // insert candidate j0+1 (distance e1)
                {
                    bool act = has && (e1 < worst) && (j0 + 1 != q);
                    float bp = __shfl_up_sync(FULLMASK, bd, 1);
                    int   ip = __shfl_up_sync(FULLMASK, bj, 1);
                    unsigned gm = __ballot_sync(FULLMASK, act && (bd > e1));
                    if (act) {
                        int pos = __ffs((gm >> (qs << 4)) & 0xFFFFu) - 1;
                        if (cs > pos)       { bd = bp; bj = ip; }
                        else if (cs == pos) { bd = fmaxf(e1, 0.0f); bj = j0 + 1; }
                    }
                    worst = fminf(thr,
                                  __shfl_sync(FULLMASK, bd, (qs << 4) + 15));
                }
            }
        }
        __syncthreads();
    }

    g_knn[q * KNN + cs] = bj;
    if (cs == KNN - 1)                      // lanes 15 and 31
        g_flag[q] = !(bd < FINF);           // incomplete -> exact fallback
}

// ============================================================
// Kernel 1b: exact fallback for flagged queries — warp per query,
// warp-distributed sorted top-16 (proven R4 insert), worst from INF.
// ============================================================
__device__ __forceinline__ void warp_insert(float dn, int jn,
                                            float& bd, int& bj,
                                            float& worst, int lane) {
    float bp = __shfl_up_sync(FULLMASK, bd, 1);
    int   ip = __shfl_up_sync(FULLMASK, bj, 1);
    unsigned gm = __ballot_sync(FULLMASK, (lane < KNN) && (bd > dn));
    int pos = __ffs(gm) - 1;            // gm != 0 since bd[15] > dn
    if (lane < KNN) {
        if (lane > pos)       { bd = bp; bj = ip; }
        else if (lane == pos) { bd = fmaxf(dn, 0.0f); bj = jn; }
    }
    worst = __shfl_sync(FULLMASK, bd, KNN - 1);
}

__global__ __launch_bounds__(256)
void knn_fallback_kernel(int n) {
    const int lane = threadIdx.x & 31;
    const int q    = blockIdx.x * 8 + (threadIdx.x >> 5);
    if (g_flag[q] == 0) return;       // warp-uniform

    const float4 qp = g_pos4[q];
    const unsigned long long qx2 = pk2(qp.x, qp.x);
    const unsigned long long qy2 = pk2(qp.y, qp.y);
    const unsigned long long qz2 = pk2(qp.z, qp.z);
    const unsigned long long qw2 = pk2(qp.w, qp.w);
    const unsigned long long M2  = pk2(-2.0f, -2.0f);

    float bd = FINF;
    int   bj = 0;
    float worst = FINF;

    for (int base = 0; base < n / 2; base += 32) {
        ulonglong2 A = g_pairA[base + lane];
        ulonglong2 B = g_pairB[base + lane];
        unsigned long long acc = mul2(qz2, B.x);
        acc = fma2(qy2, A.y, acc);
        acc = fma2(qx2, A.x, acc);
        unsigned long long dd = fma2(M2, acc, add2(qw2, B.y));
        float d0, d1;
        upk2(dd, d0, d1);

        unsigned m = __ballot_sync(FULLMASK, (d0 < worst) | (d1 < worst));
        while (m) {
            int src = __ffs(m) - 1;
            m &= m - 1;
            float e0 = __shfl_sync(FULLMASK, d0, src);
            float e1 = __shfl_sync(FULLMASK, d1, src);
            int   j0 = 2 * (base + src);
            if (e0 < worst && j0 != q)
                warp_insert(e0, j0, bd, bj, worst, lane);
            if (e1 < worst && j0 + 1 != q)
                warp_insert(e1, j0 + 1, bd, bj, worst, lane);
        }
    }

    if (lane < KNN)
        g_knn[q * KNN + lane] = bj;
}

// ============================================================
// Kernel 2: B = x @ W1b ; C = x @ (W1a - W1b) + b1
// Register-blocked x4 nodes: each W1 value loaded once per 4 nodes.
// ============================================================
__global__ __launch_bounds__(256)
void feat_kernel(const float* __restrict__ x,
                 const float* __restrict__ W1,
                 const float* __restrict__ b1, int n) {
    int t   = blockIdx.x * blockDim.x + threadIdx.x;
    int grp = t >> 6;           // group of 4 nodes
    int d   = t & 63;
    int n0  = grp * 4;
    if (n0 >= n) return;

    const float* x0 = x + n0 * CDIM;
    float a0 = 0, a1 = 0, a2 = 0, a3 = 0;
    float b0 = 0, b1v = 0, b2v = 0, b3 = 0;
#pragma unroll 8
    for (int c = 0; c < CDIM; c++) {
        float wa = W1[c * CDIM + d];            // coalesced in d
        float wb = W1[(CDIM + c) * CDIM + d];
        float x0v = x0[c];                      // warp broadcast
        float x1v = x0[CDIM + c];
        float x2v = x0[2 * CDIM + c];
        float x3v = x0[3 * CDIM + c];
        a0 = fmaf(x0v, wa, a0);  b0  = fmaf(x0v, wb, b0);
        a1 = fmaf(x1v, wa, a1);  b1v = fmaf(x1v, wb, b1v);
        a2 = fmaf(x2v, wa, a2);  b2v = fmaf(x2v, wb, b2v);
        a3 = fmaf(x3v, wa, a3);  b3  = fmaf(x3v, wb, b3);
    }
    float bias = b1[d];
    g_B[(n0 + 0) * CDIM + d] = b0;   g_C[(n0 + 0) * CDIM + d] = a0 - b0  + bias;
    g_B[(n0 + 1) * CDIM + d] = b1v;  g_C[(n0 + 1) * CDIM + d] = a1 - b1v + bias;
    g_B[(n0 + 2) * CDIM + d] = b2v;  g_C[(n0 + 2) * CDIM + d] = a2 - b2v + bias;
    g_B[(n0 + 3) * CDIM + d] = b3;   g_C[(n0 + 3) * CDIM + d] = a3 - b3  + bias;
}

// ============================================================
// Kernel 3: edge — E-OUTER restructure. The 64-register w2p array is
// gone: W2 streams one value per e from L1 (coalesced), k-accumulators
// live in 8 packed u64 regs, g comes from a TRANSPOSED smem tile
// gsT[e][k] via 4 broadcast LDS.128 per e. Regs ~60 -> occupancy ~2.3x.
// Keeps the R7 prefetch pipeline (next node's B-rows under phase2).
// ============================================================
#define GSTRIDE 20   // row pad: 80B, 16B-aligned
__global__ __launch_bounds__(64)
void edge_kernel(const float* __restrict__ W2,
                 const float* __restrict__ b2,
                 float* __restrict__ out, int n) {
    __shared__ __align__(16) float gsT[2][CDIM][GSTRIDE];  // [buf][e][k]
    const int d = threadIdx.x;
    const float b2d = b2[d];
    const int n0 = blockIdx.x * NODES_PER_BLOCK;

    // prologue: prefetch node n0
    float bv[KNN];
    float cv;
    {
        const int4* jr = (const int4*)&g_knn[n0 * KNN];
        int4 j4[4];
#pragma unroll
        for (int v = 0; v < 4; v++) j4[v] = jr[v];
        const int* jv = (const int*)j4;
        cv = g_C[n0 * CDIM + d];
#pragma unroll
        for (int k = 0; k < KNN; k++)
            bv[k] = g_B[jv[k] * CDIM + d];
    }

    for (int i = 0; i < NODES_PER_BLOCK; i++) {
        const int buf = i & 1;
        const int nn  = n0 + i;

        // phase 1: write relu'd g transposed: row e = d, cols k
#pragma unroll
        for (int k2 = 0; k2 < KNN / 2; k2++) {
            float2 gg;
            gg.x = fmaxf(cv + bv[2 * k2],     0.0f);
            gg.y = fmaxf(cv + bv[2 * k2 + 1], 0.0f);
            *(float2*)&gsT[buf][d][2 * k2] = gg;    // STS.64
        }

        // prefetch node i+1 (L2 gather hidden under phase 2)
        if (i + 1 < NODES_PER_BLOCK) {
            const int nn1 = nn + 1;
            const int4* jr = (const int4*)&g_knn[nn1 * KNN];
            int4 j4[4];
#pragma unroll
            for (int v = 0; v < 4; v++) j4[v] = jr[v];
            const int* jv = (const int*)j4;
            cv = g_C[nn1 * CDIM + d];
#pragma unroll
            for (int k = 0; k < KNN; k++)
                bv[k] = g_B[jv[k] * CDIM + d];
        }
        __syncthreads();

        // phase 2: acc[k-pair] += g[e][k]*W2[e][d], e = 0..63
        unsigned long long acc[8];
#pragma unroll
        for (int j = 0; j < 8; j++) acc[j] = 0ULL;
#pragma unroll 8
        for (int e = 0; e < CDIM; e++) {
            float wv = W2[e * CDIM + d];            // L1-hot, coalesced
            unsigned long long w2 = pk2(wv, wv);
            const ulonglong2* gp = (const ulonglong2*)&gsT[buf][e][0];
            ulonglong2 Ga = gp[0];                  // LDS.128 broadcast
            ulonglong2 Gb = gp[1];
            acc[0] = fma2(Ga.x, w2, acc[0]);
            acc[1] = fma2(Ga.y, w2, acc[1]);
            acc[2] = fma2(Gb.x, w2, acc[2]);
            acc[3] = fma2(Gb.y, w2, acc[3]);
            const ulonglong2* gq = (const ulonglong2*)&gsT[buf][e][8];
            ulonglong2 Gc = gq[0];
            ulonglong2 Gd = gq[1];
            acc[4] = fma2(Gc.x, w2, acc[4]);
            acc[5] = fma2(Gd.x, w2, acc[5]);
            acc[6] = fma2(Gc.y, w2, acc[6]);
            acc[7] = fma2(Gd.y, w2, acc[7]);
        }
        float m = -3.4e38f;
#pragma unroll
        for (int j = 0; j < 8; j++) {
            float lo, hi;
            upk2(acc[j], lo, hi);
            m = fmaxf(m, fmaxf(lo, hi));
        }
        out[nn * CDIM + d] = m + b2d;
    }
}

// ============================================================
extern "C" void kernel_launch(void* const* d_in, const int* in_sizes, int n_in,
                              void* d_out, int out_size) {
    const float* x   = (const float*)d_in[0];
    const float* pos = (const float*)d_in[1];
    const float* W1  = (const float*)d_in[2];
    const float* b1  = (const float*)d_in[3];
    const float* W2  = (const float*)d_in[4];
    const float* b2  = (const float*)d_in[5];
    float* out = (float*)d_out;

    int n = in_sizes[1] / 3;
    if (n > NMAX) n = NMAX;

    pack_pos_kernel<<<(n / 2 + 255) / 256, 256>>>(pos, n);
    knn_scan_kernel<<<n / (KNN_WARPS * 2), KNN_THREADS>>>(n);
    knn_fallback_kernel<<<n / 8, 256>>>(n);
    feat_kernel<<<(n * CDIM / 4 + 255) / 256, 256>>>(x, W1, b1, n);
    edge_kernel<<<n / NODES_PER_BLOCK, CDIM>>>(W2, b2, out, n);
}